// round 11
// baseline (speedup 1.0000x reference)
#include <cuda_runtime.h>
#include <math_constants.h>
#include <cstdint>

// ChamferLoss: B=4, N=8192, M=8192, D=3, K=1.
// EXACT 1-NN via uniform spatial grid + shell expansion with a rigorous
// distance lower-bound stopping rule, replacing brute force (268M pairs ->
// ~150 pairs/query). d^2 = |q|^2 + (|r|^2 - 2 q.r); cells store
// (-2x,-2y,-2z,|r|^2) so the inner op is 3 FFMA + 1 FMNMX.
//
// Determinism: per-query min is order-invariant (fmin over the same value
// set); results are written to g_min[qid] (natural order) and reduced in a
// fixed tree order, so atomic scatter-order variation cannot change d_out.

#define NQ       32768
#define MREF     8192
#define NCAX     48
#define NC       (NCAX * NCAX * NCAX)     // 110592 cells
#define CAP      28
#define GLO      (-5.0f)
#define GH       (10.0f / 48.0f)          // 0.2083333
#define GINVH    (48.0f / 10.0f)          // 4.8
#define RBLK     64

__device__ int    g_cnt[NC];
__device__ float4 g_cell[NC * CAP];       // (-2x, -2y, -2z, |r|^2)
__device__ float  g_min[NQ];
__device__ float  g_bsum[RBLK];

__device__ __forceinline__ int cell_coord(float v) {
    int c = (int)floorf((v - GLO) * GINVH);
    return min(max(c, 0), NCAX - 1);
}

// ---------------------------------------------------------------------------
// k1: zero cell counts
// ---------------------------------------------------------------------------
__global__ void zero_kernel() {
    int i = blockIdx.x * blockDim.x + threadIdx.x;   // 216 * 512 = NC
    g_cnt[i] = 0;
}

// ---------------------------------------------------------------------------
// k2: scatter refs into cells (rank via atomicAdd; set per cell is
// deterministic even if order is not)
// ---------------------------------------------------------------------------
__global__ void scatter_kernel(const float* __restrict__ ref) {
    int m = blockIdx.x * blockDim.x + threadIdx.x;   // 64 * 128 = MREF
    float x = ref[3 * m + 0];
    float y = ref[3 * m + 1];
    float z = ref[3 * m + 2];
    int ci = (cell_coord(z) * NCAX + cell_coord(y)) * NCAX + cell_coord(x);
    int rank = atomicAdd(&g_cnt[ci], 1);
    if (rank < CAP) {
        g_cell[ci * CAP + rank] =
            make_float4(-2.0f * x, -2.0f * y, -2.0f * z, x * x + y * y + z * z);
    }
}

// ---------------------------------------------------------------------------
// k3: per-query exact NN via shell expansion.
// After finishing shell r (box = cells [c-r, c+r]^3), any unscanned point is
// at distance >= dmin(q, box boundary). Stop when best d^2 <= dmin^2.
// ---------------------------------------------------------------------------
__device__ __forceinline__ void scan_cell(int x, int y, int z,
                                          float qx, float qy, float qz,
                                          float& best) {
    const int ci = (z * NCAX + y) * NCAX + x;
    const int n  = min(g_cnt[ci], CAP);
    const float4* __restrict__ p = &g_cell[ci * CAP];
    for (int i = 0; i < n; i++) {
        const float4 c = p[i];
        const float t = fmaf(qx, c.x, fmaf(qy, c.y, fmaf(qz, c.z, c.w)));
        best = fminf(best, t);
    }
}

__global__ void __launch_bounds__(128) query_kernel(const float* __restrict__ query) {
    const int qid = blockIdx.x * blockDim.x + threadIdx.x;  // 256*128 = NQ

    const float qx = query[3 * qid + 0];
    const float qy = query[3 * qid + 1];
    const float qz = query[3 * qid + 2];
    const float q2 = qx * qx + qy * qy + qz * qz;

    const int cx = cell_coord(qx);
    const int cy = cell_coord(qy);
    const int cz = cell_coord(qz);

    float best = CUDART_INF_F;   // min over t = |r|^2 - 2 q.r

    for (int r = 0; r < NCAX; r++) {
        const int zlo = max(cz - r, 0), zhi = min(cz + r, NCAX - 1);
        const int ylo = max(cy - r, 0), yhi = min(cy + r, NCAX - 1);
        const int xlo = max(cx - r, 0), xhi = min(cx + r, NCAX - 1);

        for (int z = zlo; z <= zhi; z++) {
            const bool zface = (z == cz - r) || (z == cz + r);
            for (int y = ylo; y <= yhi; y++) {
                const bool yface = (y == cy - r) || (y == cy + r);
                if (zface || yface) {
                    for (int x = xlo; x <= xhi; x++)
                        scan_cell(x, y, z, qx, qy, qz, best);
                } else {
                    if (cx - r >= 0)       scan_cell(cx - r, y, z, qx, qy, qz, best);
                    if (cx + r < NCAX)     scan_cell(cx + r, y, z, qx, qy, qz, best);
                }
            }
        }

        // stopping rule: distance from q to the boundary of the scanned box
        const float bxl = fmaf((float)(cx - r),     GH, GLO);
        const float bxh = fmaf((float)(cx + r + 1), GH, GLO);
        const float byl = fmaf((float)(cy - r),     GH, GLO);
        const float byh = fmaf((float)(cy + r + 1), GH, GLO);
        const float bzl = fmaf((float)(cz - r),     GH, GLO);
        const float bzh = fmaf((float)(cz + r + 1), GH, GLO);
        const float dmin = fminf(fminf(fminf(qx - bxl, bxh - qx),
                                       fminf(qy - byl, byh - qy)),
                                 fminf(qz - bzl, bzh - qz));
        const float d2 = fmaxf(q2 + best, 0.0f);
        if (dmin > 0.0f && d2 <= dmin * dmin) break;
    }

    g_min[qid] = fmaxf(q2 + best, 0.0f);
}

// ---------------------------------------------------------------------------
// k4: fixed-order partial sums: 512 queries per block
// ---------------------------------------------------------------------------
__global__ void __launch_bounds__(128) reduce1_kernel() {
    __shared__ float s[128];
    const int tid   = threadIdx.x;
    const int qbase = blockIdx.x * 512;

    float sum = 0.0f;
    #pragma unroll
    for (int k = 0; k < 4; k++) {
        sum += g_min[qbase + k * 128 + tid];
    }
    s[tid] = sum;
    __syncthreads();

    #pragma unroll
    for (int stride = 64; stride >= 1; stride >>= 1) {
        if (tid < stride) s[tid] += s[tid + stride];
        __syncthreads();
    }
    if (tid == 0) g_bsum[blockIdx.x] = s[0];
}

// ---------------------------------------------------------------------------
// k5: final 64 -> mean
// ---------------------------------------------------------------------------
__global__ void __launch_bounds__(64) reduce2_kernel(float* __restrict__ out) {
    __shared__ float s[64];
    const int tid = threadIdx.x;
    s[tid] = g_bsum[tid];
    __syncthreads();
    if (tid < 32) {
        float v = s[tid] + s[tid + 32];
        #pragma unroll
        for (int off = 16; off >= 1; off >>= 1) {
            v += __shfl_down_sync(0xFFFFFFFFu, v, off);
        }
        if (tid == 0) out[0] = v * (1.0f / (float)NQ);
    }
}

// ---------------------------------------------------------------------------
extern "C" void kernel_launch(void* const* d_in, const int* in_sizes, int n_in,
                              void* d_out, int out_size) {
    const float* query = (const float*)d_in[0];   // [4, 8192, 3] f32
    const float* ref   = (const float*)d_in[1];   // [8192, 3] f32
    (void)in_sizes; (void)n_in; (void)out_size;   // K == 1, fixed shapes
    float* out = (float*)d_out;

    zero_kernel<<<NC / 512, 512>>>();
    scatter_kernel<<<MREF / 128, 128>>>(ref);
    query_kernel<<<NQ / 128, 128>>>(query);
    reduce1_kernel<<<RBLK, 128>>>();
    reduce2_kernel<<<1, 64>>>(out);
}

// round 13
// speedup vs baseline: 3.6329x; 3.6329x over previous
#include <cuda_runtime.h>
#include <math_constants.h>
#include <cstdint>

// ChamferLoss: B=4, N=8192, M=8192, D=3, K=1.
// EXACT 1-NN: uniform grid 48^3 + shell expansion with rigorous lower-bound
// stopping rule — executed WARP-PER-QUERY (cells scanned one-per-lane, the
// stop test is warp-uniform). Cells store (-2x,-2y,-2z,|r|^2) so the inner
// op is 3 FFMA + 1 FMNMX. Overflowed points (prob ~0) go to a global list
// scanned by every warp; the min is always over all 8192 points ->
// deterministic output regardless of atomic scatter order.

#define NQ       32768
#define MREF     8192
#define NCAX     48
#define NC       (NCAX * NCAX * NCAX)     // 110592
#define CAP      16
#define OVF      512
#define GLO      (-5.0f)
#define GH       (10.0f / 48.0f)
#define GINVH    (48.0f / 10.0f)
#define RBLK     64

__device__ int    g_cnt[NC];
__device__ float4 g_cell[NC * CAP];       // 28 MB (sparse-hot)
__device__ float4 g_ovf[OVF];
__device__ int    g_ovfn;
__device__ float  g_min[NQ];
__device__ float  g_bsum[RBLK];

__device__ __forceinline__ int cell_coord(float v) {
    int c = (int)floorf((v - GLO) * GINVH);
    return min(max(c, 0), NCAX - 1);
}

// ---------------------------------------------------------------------------
// k1: zero counts + overflow counter
// ---------------------------------------------------------------------------
__global__ void zero_kernel() {
    int i = blockIdx.x * blockDim.x + threadIdx.x;   // 216 * 512 = NC
    g_cnt[i] = 0;
    if (i == 0) g_ovfn = 0;
}

// ---------------------------------------------------------------------------
// k2: scatter refs into cells; rank >= CAP -> overflow list
// ---------------------------------------------------------------------------
__global__ void scatter_kernel(const float* __restrict__ ref) {
    int m = blockIdx.x * blockDim.x + threadIdx.x;   // 64 * 128 = MREF
    float x = ref[3 * m + 0];
    float y = ref[3 * m + 1];
    float z = ref[3 * m + 2];
    float4 v = make_float4(-2.0f * x, -2.0f * y, -2.0f * z,
                           x * x + y * y + z * z);
    int ci = (cell_coord(z) * NCAX + cell_coord(y)) * NCAX + cell_coord(x);
    int rank = atomicAdd(&g_cnt[ci], 1);
    if (rank < CAP) {
        g_cell[ci * CAP + rank] = v;
    } else {
        int s = atomicAdd(&g_ovfn, 1);
        if (s < OVF) g_ovf[s] = v;
    }
}

// ---------------------------------------------------------------------------
// k3: warp-per-query exact NN
// ---------------------------------------------------------------------------
__device__ __forceinline__ void scan_cell_idx(int x, int y, int z,
                                              float qx, float qy, float qz,
                                              float& best) {
    if ((unsigned)x >= NCAX || (unsigned)y >= NCAX || (unsigned)z >= NCAX) return;
    const int ci = (z * NCAX + y) * NCAX + x;
    const int n  = min(g_cnt[ci], CAP);
    const float4* __restrict__ p = &g_cell[ci * CAP];
    for (int i = 0; i < n; i++) {
        const float4 c = p[i];
        const float t = fmaf(qx, c.x, fmaf(qy, c.y, fmaf(qz, c.z, c.w)));
        best = fminf(best, t);
    }
}

__device__ __forceinline__ float warp_min(float v) {
    #pragma unroll
    for (int off = 16; off >= 1; off >>= 1)
        v = fminf(v, __shfl_xor_sync(0xFFFFFFFFu, v, off));
    return v;
}

__global__ void __launch_bounds__(256) query_kernel(const float* __restrict__ query) {
    const int qid  = (blockIdx.x * 256 + threadIdx.x) >> 5;   // 4096 blocks
    const int lane = threadIdx.x & 31;

    const float qx = query[3 * qid + 0];   // broadcast loads
    const float qy = query[3 * qid + 1];
    const float qz = query[3 * qid + 2];
    const float q2 = qx * qx + qy * qy + qz * qz;

    const int cx = cell_coord(qx);
    const int cy = cell_coord(qy);
    const int cz = cell_coord(qz);

    float best = CUDART_INF_F;   // per-lane partial min of t = |r|^2 - 2 q.r

    for (int r = 1; r < NCAX; r++) {
        if (r == 1) {
            // full 3x3x3 box: one cell per lane, single round
            if (lane < 27) {
                const int dz = lane / 9 - 1;
                const int dy = (lane / 3) % 3 - 1;
                const int dx = lane % 3 - 1;
                scan_cell_idx(cx + dx, cy + dy, cz + dz, qx, qy, qz, best);
            }
        } else {
            // shell r only: cells of box (2r+1)^3 with Chebyshev norm == r
            const int side  = 2 * r + 1;
            const int total = side * side * side;
            for (int i = lane; i < total; i += 32) {
                const int dz = i / (side * side) - r;
                const int dy = (i / side) % side - r;
                const int dx = i % side - r;
                if (max(max(abs(dx), abs(dy)), abs(dz)) == r)
                    scan_cell_idx(cx + dx, cy + dy, cz + dz, qx, qy, qz, best);
            }
        }

        // warp-uniform stopping rule: any unscanned cell point lies at
        // distance >= dmin (dist from q to scanned-box boundary; clipped
        // faces have no points beyond them -> +INF)
        const float b = warp_min(best);
        float dmin = CUDART_INF_F;
        if (cx - r >= 0)        dmin = fminf(dmin, qx - (GLO + (float)(cx - r) * GH));
        if (cx + r < NCAX - 1)  dmin = fminf(dmin, (GLO + (float)(cx + r + 1) * GH) - qx);
        if (cy - r >= 0)        dmin = fminf(dmin, qy - (GLO + (float)(cy - r) * GH));
        if (cy + r < NCAX - 1)  dmin = fminf(dmin, (GLO + (float)(cy + r + 1) * GH) - qy);
        if (cz - r >= 0)        dmin = fminf(dmin, qz - (GLO + (float)(cz - r) * GH));
        if (cz + r < NCAX - 1)  dmin = fminf(dmin, (GLO + (float)(cz + r + 1) * GH) - qz);

        const float d2 = fmaxf(q2 + b, 0.0f);
        if (d2 <= dmin * dmin) { best = b; break; }
    }

    // overflow points: scanned by every warp (min stays over ALL 8192 pts)
    const int ovfn = min(g_ovfn, OVF);
    for (int i = lane; i < ovfn; i += 32) {
        const float4 c = g_ovf[i];
        const float t = fmaf(qx, c.x, fmaf(qy, c.y, fmaf(qz, c.z, c.w)));
        best = fminf(best, t);
    }

    const float b = warp_min(best);
    if (lane == 0) g_min[qid] = fmaxf(q2 + b, 0.0f);
}

// ---------------------------------------------------------------------------
// k4: fixed-order partial sums: 512 queries per block
// ---------------------------------------------------------------------------
__global__ void __launch_bounds__(128) reduce1_kernel() {
    __shared__ float s[128];
    const int tid   = threadIdx.x;
    const int qbase = blockIdx.x * 512;

    float sum = 0.0f;
    #pragma unroll
    for (int k = 0; k < 4; k++) {
        sum += g_min[qbase + k * 128 + tid];
    }
    s[tid] = sum;
    __syncthreads();

    #pragma unroll
    for (int stride = 64; stride >= 1; stride >>= 1) {
        if (tid < stride) s[tid] += s[tid + stride];
        __syncthreads();
    }
    if (tid == 0) g_bsum[blockIdx.x] = s[0];
}

// ---------------------------------------------------------------------------
// k5: final 64 -> mean
// ---------------------------------------------------------------------------
__global__ void __launch_bounds__(64) reduce2_kernel(float* __restrict__ out) {
    __shared__ float s[64];
    const int tid = threadIdx.x;
    s[tid] = g_bsum[tid];
    __syncthreads();
    if (tid < 32) {
        float v = s[tid] + s[tid + 32];
        #pragma unroll
        for (int off = 16; off >= 1; off >>= 1) {
            v += __shfl_down_sync(0xFFFFFFFFu, v, off);
        }
        if (tid == 0) out[0] = v * (1.0f / (float)NQ);
    }
}

// ---------------------------------------------------------------------------
extern "C" void kernel_launch(void* const* d_in, const int* in_sizes, int n_in,
                              void* d_out, int out_size) {
    const float* query = (const float*)d_in[0];   // [4, 8192, 3] f32
    const float* ref   = (const float*)d_in[1];   // [8192, 3] f32
    (void)in_sizes; (void)n_in; (void)out_size;   // K == 1, fixed shapes
    float* out = (float*)d_out;

    zero_kernel<<<NC / 512, 512>>>();
    scatter_kernel<<<MREF / 128, 128>>>(ref);
    query_kernel<<<NQ / 8, 256>>>(query);
    reduce1_kernel<<<RBLK, 128>>>();
    reduce2_kernel<<<1, 64>>>(out);
}

// round 14
// speedup vs baseline: 4.3703x; 1.2030x over previous
#include <cuda_runtime.h>
#include <math_constants.h>
#include <cstdint>

// ChamferLoss: B=4, N=8192, M=8192, D=3, K=1 — exact grid NN.
// Grid 32^3 (h=0.3125) over [-5,5]. Refs binned (CAP_R=32/cell + tiny
// overflow list). Queries binned (CAP_Q=192/cell, overflow -> fallback).
// solve_kernel: CTA per query cell, stages the 27-cell ref neighborhood
// COMPACTED into smem (coalesced), every thread scans the same list
// (LDS broadcast, divergence-free). Any unstaged ref is >= h away, so
// d^2 <= h^2 proves exactness; the rest go to a shell-expansion fallback
// (validated in R11/R12) over ~1-3% of queries.
// Cells store (-2x,-2y,-2z,|r|^2): inner op = 3 FFMA + 1 FMNMX.
// Determinism: g_min[qid] depends only on qid; reductions fixed-order.

#define NQ       32768
#define MREF     8192
#define NCAX     32
#define NC       (NCAX * NCAX * NCAX)    // 32768
#define CAP_R    32
#define CAP_Q    192
#define OVF      512
#define GLO      (-5.0f)
#define GH       (10.0f / 32.0f)         // 0.3125
#define GINVH    3.2f
#define H2       (GH * GH)               // 0.09765625
#define RBLK     64
#define SOLVE_CTAS 2048

__device__ int    g_rcnt[NC];
__device__ float4 g_rcell[NC * CAP_R];   // 16.8 MB
__device__ float4 g_ovf[OVF];
__device__ int    g_rovfn;
__device__ int    g_qcnt[NC];
__device__ int    g_qcell[NC * CAP_Q];   // 25 MB
__device__ int    g_fb[NQ];
__device__ int    g_fbn;
__device__ float  g_min[NQ];
__device__ float  g_bsum[RBLK];

__device__ __forceinline__ int cell_coord(float v) {
    int c = (int)floorf((v - GLO) * GINVH);
    return min(max(c, 0), NCAX - 1);
}

// ---------------------------------------------------------------------------
// k1: zero counts + counters
// ---------------------------------------------------------------------------
__global__ void zero_kernel() {
    int i = blockIdx.x * blockDim.x + threadIdx.x;   // 256*128 = NC
    g_rcnt[i] = 0;
    g_qcnt[i] = 0;
    if (i == 0) { g_rovfn = 0; g_fbn = 0; }
}

// ---------------------------------------------------------------------------
// k2: scatter refs
// ---------------------------------------------------------------------------
__global__ void scatter_ref_kernel(const float* __restrict__ ref) {
    int m = blockIdx.x * blockDim.x + threadIdx.x;   // 64*128 = MREF
    float x = ref[3 * m + 0];
    float y = ref[3 * m + 1];
    float z = ref[3 * m + 2];
    float4 v = make_float4(-2.0f * x, -2.0f * y, -2.0f * z,
                           x * x + y * y + z * z);
    int ci = (cell_coord(z) * NCAX + cell_coord(y)) * NCAX + cell_coord(x);
    int rank = atomicAdd(&g_rcnt[ci], 1);
    if (rank < CAP_R) {
        g_rcell[ci * CAP_R + rank] = v;
    } else {
        int s = atomicAdd(&g_rovfn, 1);
        if (s < OVF) g_ovf[s] = v;
    }
}

// ---------------------------------------------------------------------------
// k3: scatter queries (overflow -> fallback list)
// ---------------------------------------------------------------------------
__global__ void scatter_query_kernel(const float* __restrict__ query) {
    int q = blockIdx.x * blockDim.x + threadIdx.x;   // 256*128 = NQ
    float x = query[3 * q + 0];
    float y = query[3 * q + 1];
    float z = query[3 * q + 2];
    int ci = (cell_coord(z) * NCAX + cell_coord(y)) * NCAX + cell_coord(x);
    int rank = atomicAdd(&g_qcnt[ci], 1);
    if (rank < CAP_Q) {
        g_qcell[ci * CAP_Q + rank] = q;
    } else {
        g_fb[atomicAdd(&g_fbn, 1)] = q;
    }
}

// ---------------------------------------------------------------------------
// k4: solve — CTA per query cell (grid-stride), staged compact smem scan
// ---------------------------------------------------------------------------
__global__ void __launch_bounds__(128) solve_kernel(const float* __restrict__ query) {
    __shared__ __align__(16) float4 s_pts[27 * CAP_R + 4];
    __shared__ int s_cnt[27];
    __shared__ int s_cid[27];
    __shared__ int s_pref[28];

    const int tid = threadIdx.x;

    for (int cell = blockIdx.x; cell < NC; cell += SOLVE_CTAS) {
        int nq = g_qcnt[cell];
        if (nq == 0) continue;
        nq = min(nq, CAP_Q);

        const int cz = cell >> 10;
        const int cy = (cell >> 5) & 31;
        const int cx = cell & 31;

        __syncthreads();   // protect smem from previous cell's readers

        if (tid < 27) {
            const int dz = tid / 9 - 1;
            const int dy = (tid / 3) % 3 - 1;
            const int dx = tid % 3 - 1;
            const int x = cx + dx, y = cy + dy, z = cz + dz;
            int cnt = 0, ci = 0;
            if ((unsigned)x < NCAX && (unsigned)y < NCAX && (unsigned)z < NCAX) {
                ci = (z << 10) | (y << 5) | x;
                cnt = min(g_rcnt[ci], CAP_R);
            }
            s_cnt[tid] = cnt;
            s_cid[tid] = ci;
        }
        __syncthreads();

        // exclusive prefix over 27 counts (warp 0)
        if (tid < 32) {
            int v = (tid < 27) ? s_cnt[tid] : 0;
            int incl = v;
            #pragma unroll
            for (int off = 1; off < 32; off <<= 1) {
                int n = __shfl_up_sync(0xFFFFFFFFu, incl, off);
                if (tid >= off) incl += n;
            }
            if (tid < 27) s_pref[tid] = incl - v;
            if (tid == 26) s_pref[27] = incl;
        }
        __syncthreads();

        const int T = s_pref[27];

        // compact staging: coalesced reads, compact writes
        for (int slot = tid; slot < 27 * CAP_R; slot += 128) {
            const int c = slot >> 5;          // CAP_R = 32
            const int i = slot & (CAP_R - 1);
            if (i < s_cnt[c]) {
                s_pts[s_pref[c] + i] = g_rcell[s_cid[c] * CAP_R + i];
            }
        }
        if (tid < 4) s_pts[T + tid] = make_float4(0.f, 0.f, 0.f, 3.0e38f);
        __syncthreads();

        const int T4 = (T + 3) & ~3;

        for (int j = tid; j < nq; j += 128) {
            const int qid = g_qcell[cell * CAP_Q + j];
            const float qx = query[3 * qid + 0];
            const float qy = query[3 * qid + 1];
            const float qz = query[3 * qid + 2];
            const float q2 = qx * qx + qy * qy + qz * qz;

            float b0 = CUDART_INF_F, b1 = CUDART_INF_F;
            float b2 = CUDART_INF_F, b3 = CUDART_INF_F;
            for (int i = 0; i < T4; i += 4) {
                const float4 c0 = s_pts[i + 0];
                const float4 c1 = s_pts[i + 1];
                const float4 c2 = s_pts[i + 2];
                const float4 c3 = s_pts[i + 3];
                b0 = fminf(b0, fmaf(qx, c0.x, fmaf(qy, c0.y, fmaf(qz, c0.z, c0.w))));
                b1 = fminf(b1, fmaf(qx, c1.x, fmaf(qy, c1.y, fmaf(qz, c1.z, c1.w))));
                b2 = fminf(b2, fmaf(qx, c2.x, fmaf(qy, c2.y, fmaf(qz, c2.z, c2.w))));
                b3 = fminf(b3, fmaf(qx, c3.x, fmaf(qy, c3.y, fmaf(qz, c3.z, c3.w))));
            }
            float best = fminf(fminf(b0, b1), fminf(b2, b3));

            // overflow refs (normally zero)
            const int on = min(g_rovfn, OVF);
            for (int i = 0; i < on; i++) {
                const float4 c = g_ovf[i];
                best = fminf(best, fmaf(qx, c.x, fmaf(qy, c.y, fmaf(qz, c.z, c.w))));
            }

            const float d2 = fmaxf(q2 + best, 0.0f);
            if (d2 <= H2) {
                g_min[qid] = d2;     // exact: unstaged refs are >= h away
            } else {
                g_fb[atomicAdd(&g_fbn, 1)] = qid;
            }
        }
    }
}

// ---------------------------------------------------------------------------
// k5: fallback — warp-per-query shell expansion (R11-validated logic)
// ---------------------------------------------------------------------------
__device__ __forceinline__ void scan_cell_idx(int x, int y, int z,
                                              float qx, float qy, float qz,
                                              float& best) {
    if ((unsigned)x >= NCAX || (unsigned)y >= NCAX || (unsigned)z >= NCAX) return;
    const int ci = (z << 10) | (y << 5) | x;
    const int n  = min(g_rcnt[ci], CAP_R);
    const float4* __restrict__ p = &g_rcell[ci * CAP_R];
    for (int i = 0; i < n; i++) {
        const float4 c = p[i];
        best = fminf(best, fmaf(qx, c.x, fmaf(qy, c.y, fmaf(qz, c.z, c.w))));
    }
}

__device__ __forceinline__ float warp_min(float v) {
    #pragma unroll
    for (int off = 16; off >= 1; off >>= 1)
        v = fminf(v, __shfl_xor_sync(0xFFFFFFFFu, v, off));
    return v;
}

__global__ void __launch_bounds__(256) fallback_kernel(const float* __restrict__ query) {
    const int gw   = (blockIdx.x * 256 + threadIdx.x) >> 5;
    const int lane = threadIdx.x & 31;
    const int nw   = (gridDim.x * 256) >> 5;
    const int nfb  = min(g_fbn, NQ);

    for (int fi = gw; fi < nfb; fi += nw) {
        const int qid = g_fb[fi];
        const float qx = query[3 * qid + 0];
        const float qy = query[3 * qid + 1];
        const float qz = query[3 * qid + 2];
        const float q2 = qx * qx + qy * qy + qz * qz;

        const int cx = cell_coord(qx);
        const int cy = cell_coord(qy);
        const int cz = cell_coord(qz);

        float best = CUDART_INF_F;

        // overflow refs first (min over ALL points regardless of cells)
        const int on = min(g_rovfn, OVF);
        for (int i = lane; i < on; i += 32) {
            const float4 c = g_ovf[i];
            best = fminf(best, fmaf(qx, c.x, fmaf(qy, c.y, fmaf(qz, c.z, c.w))));
        }

        for (int r = 1; r < NCAX; r++) {
            if (r == 1) {
                if (lane < 27) {
                    const int dz = lane / 9 - 1;
                    const int dy = (lane / 3) % 3 - 1;
                    const int dx = lane % 3 - 1;
                    scan_cell_idx(cx + dx, cy + dy, cz + dz, qx, qy, qz, best);
                }
            } else {
                const int side  = 2 * r + 1;
                const int total = side * side * side;
                for (int i = lane; i < total; i += 32) {
                    const int dz = i / (side * side) - r;
                    const int dy = (i / side) % side - r;
                    const int dx = i % side - r;
                    if (max(max(abs(dx), abs(dy)), abs(dz)) == r)
                        scan_cell_idx(cx + dx, cy + dy, cz + dz, qx, qy, qz, best);
                }
            }

            const float b = warp_min(best);
            float dmin = CUDART_INF_F;
            if (cx - r >= 0)        dmin = fminf(dmin, qx - (GLO + (float)(cx - r) * GH));
            if (cx + r < NCAX - 1)  dmin = fminf(dmin, (GLO + (float)(cx + r + 1) * GH) - qx);
            if (cy - r >= 0)        dmin = fminf(dmin, qy - (GLO + (float)(cy - r) * GH));
            if (cy + r < NCAX - 1)  dmin = fminf(dmin, (GLO + (float)(cy + r + 1) * GH) - qy);
            if (cz - r >= 0)        dmin = fminf(dmin, qz - (GLO + (float)(cz - r) * GH));
            if (cz + r < NCAX - 1)  dmin = fminf(dmin, (GLO + (float)(cz + r + 1) * GH) - qz);

            const float d2 = fmaxf(q2 + b, 0.0f);
            if (d2 <= dmin * dmin) { best = b; break; }
        }

        const float b = warp_min(best);
        if (lane == 0) g_min[qid] = fmaxf(q2 + b, 0.0f);
    }
}

// ---------------------------------------------------------------------------
// k6: fixed-order partial sums, 512 queries/block
// ---------------------------------------------------------------------------
__global__ void __launch_bounds__(128) reduce1_kernel() {
    __shared__ float s[128];
    const int tid   = threadIdx.x;
    const int qbase = blockIdx.x * 512;

    float sum = 0.0f;
    #pragma unroll
    for (int k = 0; k < 4; k++) sum += g_min[qbase + k * 128 + tid];
    s[tid] = sum;
    __syncthreads();

    #pragma unroll
    for (int stride = 64; stride >= 1; stride >>= 1) {
        if (tid < stride) s[tid] += s[tid + stride];
        __syncthreads();
    }
    if (tid == 0) g_bsum[blockIdx.x] = s[0];
}

// ---------------------------------------------------------------------------
// k7: final 64 -> mean
// ---------------------------------------------------------------------------
__global__ void __launch_bounds__(64) reduce2_kernel(float* __restrict__ out) {
    __shared__ float s[64];
    const int tid = threadIdx.x;
    s[tid] = g_bsum[tid];
    __syncthreads();
    if (tid < 32) {
        float v = s[tid] + s[tid + 32];
        #pragma unroll
        for (int off = 16; off >= 1; off >>= 1)
            v += __shfl_down_sync(0xFFFFFFFFu, v, off);
        if (tid == 0) out[0] = v * (1.0f / (float)NQ);
    }
}

// ---------------------------------------------------------------------------
extern "C" void kernel_launch(void* const* d_in, const int* in_sizes, int n_in,
                              void* d_out, int out_size) {
    const float* query = (const float*)d_in[0];   // [4, 8192, 3] f32
    const float* ref   = (const float*)d_in[1];   // [8192, 3] f32
    (void)in_sizes; (void)n_in; (void)out_size;   // K == 1, fixed shapes
    float* out = (float*)d_out;

    zero_kernel<<<NC / 128, 128>>>();
    scatter_ref_kernel<<<MREF / 128, 128>>>(ref);
    scatter_query_kernel<<<NQ / 128, 128>>>(query);
    solve_kernel<<<SOLVE_CTAS, 128>>>(query);
    fallback_kernel<<<128, 256>>>(query);
    reduce1_kernel<<<RBLK, 128>>>();
    reduce2_kernel<<<1, 64>>>(out);
}